// round 11
// baseline (speedup 1.0000x reference)
#include <cuda_runtime.h>
#include <cstdint>

// Problem constants (shapes are fixed by the dataset).
static constexpr int cN = 300000;
static constexpr int cE = 1500000;
static constexpr int cG = 30000;

// Scratch (device globals — no allocation allowed). Zero-initialized at load;
// the transform kernels re-zero agg1/agg2 each call to keep the invariant.
__device__ float g_x0[(size_t)cN * 32];
__device__ float g_h1[(size_t)cN * 64];
__device__ float g_h2[(size_t)cN * 64];
__device__ float g_agg1[(size_t)cN * 3 * 32];   // layer-1 aggregates [N][3][32]
__device__ float g_agg2[(size_t)cN * 3 * 64];   // layer-2 aggregates [N][3][64]
__device__ int   g_cnt[(size_t)cN * 3];
__device__ float g_inv[(size_t)cN * 3];
__device__ float g_gsum[(size_t)cG * 64];
__device__ int   g_gcnt[cG];

// ---------------------------------------------------------------------------
// Per-(dst, relation) in-degree counts.
__global__ void count_kernel(const int* __restrict__ ei, const int* __restrict__ et,
                             int* __restrict__ cnt, int E) {
    int e = blockIdx.x * blockDim.x + threadIdx.x;
    if (e >= E) return;
    atomicAdd(&cnt[ei[E + e] * 3 + et[e]], 1);
}

// inv[i] = 1 / max(cnt[i], 1)
__global__ void inv_kernel(const int* __restrict__ cnt, float* __restrict__ inv, int M) {
    int i = blockIdx.x * blockDim.x + threadIdx.x;
    if (i >= M) return;
    inv[i] = __fdividef(1.0f, (float)max(cnt[i], 1));
}

// Node features: x0 = shape_emb[sid] + col_emb[cid] + pos_emb[pid]  (N x 32)
__global__ void features_kernel(const int* __restrict__ sid, const int* __restrict__ cid,
                                const int* __restrict__ pid,
                                const float* __restrict__ se, const float* __restrict__ ce,
                                const float* __restrict__ pe,
                                float* __restrict__ x0, int N) {
    int t = blockIdx.x * blockDim.x + threadIdx.x;
    int n = t >> 3, q = t & 7;
    if (n >= N) return;
    float4 a = ((const float4*)(se + (size_t)sid[n] * 32))[q];
    float4 b = ((const float4*)(ce + (size_t)cid[n] * 32))[q];
    float4 c = ((const float4*)(pe + (size_t)pid[n] * 32))[q];
    ((float4*)(x0 + (size_t)n * 32))[q] =
        make_float4(a.x + b.x + c.x, a.y + b.y + c.y, a.z + b.z + c.z, a.w + b.w + c.w);
}

// Edge aggregation: agg[dst][et][*] += x[src][*] * inv[dst][et]
template <int D>
__global__ void edge_agg_kernel(const float* __restrict__ xin,
                                const int* __restrict__ ei,
                                const int* __restrict__ et,
                                const float* __restrict__ inv,
                                float* __restrict__ agg, int E) {
    constexpr int L = D / 4;
    int t = blockIdx.x * blockDim.x + threadIdx.x;
    int e = t / L, q = t % L;
    if (e >= E) return;
    int s = ei[e], d = ei[E + e], r = et[e];
    int slot = d * 3 + r;
    float w = inv[slot];
    float4 v = ((const float4*)(xin + (size_t)s * D))[q];
    float* o = agg + (size_t)slot * D + q * 4;
    asm volatile("red.global.add.v4.f32 [%0], {%1, %2, %3, %4};"
                 :: "l"(o), "f"(v.x * w), "f"(v.y * w), "f"(v.z * w), "f"(v.w * w)
                 : "memory");
}

// ---------------------------------------------------------------------------
// mma.sync tf32 m16n8k8 (Ampere-compatible PTX -> fallback HMMA on sm_103a).
__device__ __forceinline__ void mma8(float* c, const uint32_t* a,
                                     uint32_t b0, uint32_t b1) {
    asm volatile(
        "mma.sync.aligned.m16n8k8.row.col.f32.tf32.tf32.f32 "
        "{%0,%1,%2,%3}, {%4,%5,%6,%7}, {%8,%9}, {%0,%1,%2,%3};"
        : "+f"(c[0]), "+f"(c[1]), "+f"(c[2]), "+f"(c[3])
        : "r"(a[0]), "r"(a[1]), "r"(a[2]), "r"(a[3]), "r"(b0), "r"(b1));
}
__device__ __forceinline__ uint32_t tf32m(float v) {
    return __float_as_uint(v) & 0xFFFFE000u;
}

// tf32x3 tensor-core fused transform:
//   out[tile 256 nodes][64] = relu( bias + A[256][KTOT] @ Wfull[KTOT][64] )
// A = concat(agg row, x row); Wfull = vstack(W_r..., root).
// A,B split hi/lo tf32; acc += Ah*Bh + Ah*Bl + Al*Bh in fp32 (rel err ~1e-6).
//
// Per block (256 thr): B resident in smem (XOR-swizzled [K][64], conflict-free
// fragment LDS); A staged per 32-wide K chunk, [256][36] stride (bank = 4m+k:
// conflict-free fragment LDS). Warp owns 32 nodes = two m16 strips; per k-step:
// 16 A-LDS + 8 n-blocks x (4 B-LDS + 6 mma).
// Epilogue writes out + zero-folds the OTHER layer's agg buffer.
template <int D, bool RELU>
__global__ void __launch_bounds__(256, 1)
transform_mma_kernel(const float* __restrict__ agg,
                     const float* __restrict__ xin,
                     const float* __restrict__ W,     // [3*D][64]
                     const float* __restrict__ root,  // [D][64]
                     const float* __restrict__ bias,  // [64]
                     float* __restrict__ out,
                     float* __restrict__ zbuf, int zf4,
                     int N) {
    constexpr int KTOT = 4 * D;          // 128 / 256
    constexpr int NCH  = KTOT / 32;      // K chunks of 32
    constexpr int AQ   = 3 * D / 4;      // agg float4s per node
    constexpr int XQ   = D / 4;          // x   float4s per node
    extern __shared__ float sm[];
    float* sb = sm;                       // bias [64]
    float* Bh = sm + 64;                  // [KTOT][64] hi, XOR-swizzled
    float* Bl = Bh + KTOT * 64;           // lo
    float* Ah = Bl + KTOT * 64;           // [256][36] hi chunk
    float* Al = Ah + 256 * 36;            // lo chunk

    int tid = threadIdx.x;
    int w = tid >> 5, l = tid & 31;
    int grp = l >> 2, tig = l & 3;

    if (tid < 64) sb[tid] = bias[tid];
    // Stage B once: hi/lo tf32, swizzled col = n ^ ((k&3)<<3).
    for (int i = tid; i < KTOT * 64; i += 256) {
        int k = i >> 6, n = i & 63;
        float v = (k < 3 * D) ? W[(size_t)k * 64 + n] : root[(size_t)(k - 3 * D) * 64 + n];
        uint32_t hb = tf32m(v);
        uint32_t lb = tf32m(v - __uint_as_float(hb));
        int col = n ^ ((k & 3) << 3);
        ((uint32_t*)Bh)[k * 64 + col] = hb;
        ((uint32_t*)Bl)[k * 64 + col] = lb;
    }
    __syncthreads();

    const uint32_t* Bhu = (const uint32_t*)Bh;
    const uint32_t* Blu = (const uint32_t*)Bl;
    const uint32_t* Ahu = (const uint32_t*)Ah;
    const uint32_t* Alu = (const uint32_t*)Al;

    for (int tile = blockIdx.x * 256; tile < N; tile += gridDim.x * 256) {
        float acc[2][8][4];
#pragma unroll
        for (int t = 0; t < 2; t++)
#pragma unroll
            for (int nb = 0; nb < 8; nb++) {
                int bc = nb * 8 + 2 * tig;
                acc[t][nb][0] = sb[bc];
                acc[t][nb][1] = sb[bc + 1];
                acc[t][nb][2] = sb[bc];
                acc[t][nb][3] = sb[bc + 1];
            }

        for (int c = 0; c < NCH; c++) {
            __syncthreads();   // all warps done reading previous A chunk
            // Stage A chunk c: 256 nodes x 8 float4, hi/lo split.
#pragma unroll
            for (int it = 0; it < 8; it++) {
                int i = tid + (it << 8);
                int row = i >> 3, kq = i & 7;
                int node = tile + row;
                float4 v = make_float4(0.f, 0.f, 0.f, 0.f);
                int gq = c * 8 + kq;
                if (node < N) {
                    if (gq < AQ) v = ((const float4*)agg)[(size_t)node * AQ + gq];
                    else         v = ((const float4*)xin)[(size_t)node * XQ + gq - AQ];
                }
                float4 h = make_float4(__uint_as_float(tf32m(v.x)), __uint_as_float(tf32m(v.y)),
                                       __uint_as_float(tf32m(v.z)), __uint_as_float(tf32m(v.w)));
                float4 lo = make_float4(__uint_as_float(tf32m(v.x - h.x)),
                                        __uint_as_float(tf32m(v.y - h.y)),
                                        __uint_as_float(tf32m(v.z - h.z)),
                                        __uint_as_float(tf32m(v.w - h.w)));
                *(float4*)(Ah + row * 36 + kq * 4) = h;
                *(float4*)(Al + row * 36 + kq * 4) = lo;
            }
            __syncthreads();

#pragma unroll
            for (int ks = 0; ks < 4; ks++) {
                int kc = ks * 8 + tig;
                uint32_t ah[2][4], al[2][4];
#pragma unroll
                for (int t = 0; t < 2; t++) {
                    int r0 = (w << 5) + (t << 4) + grp;
                    ah[t][0] = Ahu[r0 * 36 + kc];
                    ah[t][1] = Ahu[(r0 + 8) * 36 + kc];
                    ah[t][2] = Ahu[r0 * 36 + kc + 4];
                    ah[t][3] = Ahu[(r0 + 8) * 36 + kc + 4];
                    al[t][0] = Alu[r0 * 36 + kc];
                    al[t][1] = Alu[(r0 + 8) * 36 + kc];
                    al[t][2] = Alu[r0 * 36 + kc + 4];
                    al[t][3] = Alu[(r0 + 8) * 36 + kc + 4];
                }
                int kg = c * 32 + ks * 8 + tig;
                int co = tig << 3;
#pragma unroll
                for (int nb = 0; nb < 8; nb++) {
                    int col = (((nb << 3) ^ co) + grp);
                    uint32_t bh0 = Bhu[kg * 64 + col];
                    uint32_t bh1 = Bhu[(kg + 4) * 64 + col];
                    uint32_t bl0 = Blu[kg * 64 + col];
                    uint32_t bl1 = Blu[(kg + 4) * 64 + col];
                    mma8(acc[0][nb], ah[0], bh0, bh1);
                    mma8(acc[0][nb], ah[0], bl0, bl1);
                    mma8(acc[0][nb], al[0], bh0, bh1);
                    mma8(acc[1][nb], ah[1], bh0, bh1);
                    mma8(acc[1][nb], ah[1], bl0, bl1);
                    mma8(acc[1][nb], al[1], bh0, bh1);
                }
            }
        }

        // Epilogue: c0,c1 -> row grp; c2,c3 -> row grp+8; cols nb*8 + 2*tig.
#pragma unroll
        for (int t = 0; t < 2; t++) {
            int n0 = tile + (w << 5) + (t << 4) + grp;
#pragma unroll
            for (int nb = 0; nb < 8; nb++) {
                int colf = nb * 8 + 2 * tig;
                float2 v0 = make_float2(acc[t][nb][0], acc[t][nb][1]);
                float2 v1 = make_float2(acc[t][nb][2], acc[t][nb][3]);
                if (RELU) {
                    v0.x = fmaxf(v0.x, 0.f); v0.y = fmaxf(v0.y, 0.f);
                    v1.x = fmaxf(v1.x, 0.f); v1.y = fmaxf(v1.y, 0.f);
                }
                if (n0 < N)     *(float2*)(out + (size_t)n0 * 64 + colf) = v0;
                if (n0 + 8 < N) *(float2*)(out + (size_t)(n0 + 8) * 64 + colf) = v1;
            }
        }

        // Zero-fold: clear the other layer's agg buffer for this node tile.
        {
            const float4 z4 = make_float4(0.f, 0.f, 0.f, 0.f);
            size_t lim = (size_t)N * zf4;
            for (int i = tid; i < 256 * zf4; i += 256) {
                size_t idx = (size_t)tile * zf4 + i;
                if (idx < lim) ((float4*)zbuf)[idx] = z4;
            }
        }
    }
}

// Global mean pool (sum + count); 16 lanes per node, vector RED.
__global__ void pool_kernel(const float* __restrict__ h, const int* __restrict__ batch,
                            float* __restrict__ gsum, int* __restrict__ gcnt, int N) {
    int t = blockIdx.x * blockDim.x + threadIdx.x;
    int n = t >> 4, q = t & 15;
    if (n >= N) return;
    int b = batch[n];
    float4 v = ((const float4*)(h + (size_t)n * 64))[q];
    float* o = gsum + (size_t)b * 64 + q * 4;
    asm volatile("red.global.add.v4.f32 [%0], {%1, %2, %3, %4};"
                 :: "l"(o), "f"(v.x), "f"(v.y), "f"(v.z), "f"(v.w)
                 : "memory");
    if (q == 0) atomicAdd(&gcnt[b], 1);
}

// Final: out[g] = (gsum[g]/max(cnt,1)) @ lin_W + lin_b. One warp per graph.
__global__ void pool_final_kernel(const float* __restrict__ gsum, const int* __restrict__ gcnt,
                                  const float* __restrict__ lw, const float* __restrict__ lb,
                                  float* __restrict__ out, int G) {
    int t = blockIdx.x * blockDim.x + threadIdx.x;
    int g = t >> 5, lane = t & 31;
    if (g >= G) return;
    float2 v = ((const float2*)(gsum + (size_t)g * 64))[lane];
    int k0 = 2 * lane, k1 = 2 * lane + 1;
    float a0 = v.x * lw[k0 * 2 + 0] + v.y * lw[k1 * 2 + 0];
    float a1 = v.x * lw[k0 * 2 + 1] + v.y * lw[k1 * 2 + 1];
#pragma unroll
    for (int off = 16; off; off >>= 1) {
        a0 += __shfl_down_sync(0xffffffff, a0, off);
        a1 += __shfl_down_sync(0xffffffff, a1, off);
    }
    if (lane == 0) {
        float c = fmaxf((float)gcnt[g], 1.0f);
        out[g * 2 + 0] = a0 / c + lb[0];
        out[g * 2 + 1] = a1 / c + lb[1];
    }
}

// ---------------------------------------------------------------------------
extern "C" void kernel_launch(void* const* d_in, const int* in_sizes, int n_in,
                              void* d_out, int out_size) {
    const int*   sid   = (const int*)d_in[0];
    const int*   cid   = (const int*)d_in[1];
    const int*   pid   = (const int*)d_in[2];
    const int*   ei    = (const int*)d_in[3];   // [2, E]: row0 = src, row1 = dst
    const int*   et    = (const int*)d_in[4];
    const int*   batch = (const int*)d_in[5];
    // d_in[6] = num_graphs (scalar), unused
    const float* se = (const float*)d_in[7];
    const float* ce = (const float*)d_in[8];
    const float* pe = (const float*)d_in[9];
    const float* W1 = (const float*)d_in[10];
    const float* r1 = (const float*)d_in[11];
    const float* b1 = (const float*)d_in[12];
    const float* W2 = (const float*)d_in[13];
    const float* r2 = (const float*)d_in[14];
    const float* b2 = (const float*)d_in[15];
    const float* lw = (const float*)d_in[16];
    const float* lb = (const float*)d_in[17];
    float* out = (float*)d_out;

    const int N = in_sizes[0];
    const int E = in_sizes[4];
    const int G = out_size / 2;

    void *p_x0, *p_h1, *p_h2, *p_agg1, *p_agg2, *p_cnt, *p_inv, *p_gsum, *p_gcnt;
    cudaGetSymbolAddress(&p_x0, g_x0);
    cudaGetSymbolAddress(&p_h1, g_h1);
    cudaGetSymbolAddress(&p_h2, g_h2);
    cudaGetSymbolAddress(&p_agg1, g_agg1);
    cudaGetSymbolAddress(&p_agg2, g_agg2);
    cudaGetSymbolAddress(&p_cnt, g_cnt);
    cudaGetSymbolAddress(&p_inv, g_inv);
    cudaGetSymbolAddress(&p_gsum, g_gsum);
    cudaGetSymbolAddress(&p_gcnt, g_gcnt);

    // smem (floats): 64 bias + 2*K*64 B + 2*256*36 A
    //   layer1 (K=128): (64 + 16384 + 18432)*4 = 139520 B
    //   layer2 (K=256): (64 + 32768 + 18432)*4 = 205056 B
    const int SMEM1 = 139520, SMEM2 = 205056;
    cudaFuncSetAttribute(transform_mma_kernel<32, true>,
                         cudaFuncAttributeMaxDynamicSharedMemorySize, SMEM1);
    cudaFuncSetAttribute(transform_mma_kernel<64, true>,
                         cudaFuncAttributeMaxDynamicSharedMemorySize, SMEM2);

    cudaMemsetAsync(p_cnt, 0, (size_t)N * 3 * sizeof(int));
    cudaMemsetAsync(p_gsum, 0, (size_t)G * 64 * sizeof(float));
    cudaMemsetAsync(p_gcnt, 0, (size_t)G * sizeof(int));

    count_kernel<<<(E + 255) / 256, 256>>>(ei, et, (int*)p_cnt, E);
    inv_kernel<<<(N * 3 + 255) / 256, 256>>>((const int*)p_cnt, (float*)p_inv, N * 3);
    features_kernel<<<(N * 8 + 255) / 256, 256>>>(sid, cid, pid, se, ce, pe, (float*)p_x0, N);

    // ---- Layer 1 (D = 32) ----
    // agg1 was zeroed by the previous call's transform (or load-time init).
    edge_agg_kernel<32><<<(E * 8 + 255) / 256, 256>>>(
        (const float*)p_x0, ei, et, (const float*)p_inv, (float*)p_agg1, E);
    transform_mma_kernel<32, true><<<148, 256, SMEM1>>>(
        (const float*)p_agg1, (const float*)p_x0, W1, r1, b1, (float*)p_h1,
        (float*)p_agg2, 3 * 64 / 4, N);   // zero agg2 for layer 2

    // ---- Layer 2 (D = 64) ----
    edge_agg_kernel<64><<<(E * 16 + 255) / 256, 256>>>(
        (const float*)p_h1, ei, et, (const float*)p_inv, (float*)p_agg2, E);
    transform_mma_kernel<64, true><<<148, 256, SMEM2>>>(
        (const float*)p_agg2, (const float*)p_h1, W2, r2, b2, (float*)p_h2,
        (float*)p_agg1, 3 * 32 / 4, N);   // zero agg1 for the next call

    // ---- Pool + head ----
    pool_kernel<<<(N * 16 + 255) / 256, 256>>>(
        (const float*)p_h2, batch, (float*)p_gsum, (int*)p_gcnt, N);
    pool_final_kernel<<<(G * 32 + 255) / 256, 256>>>(
        (const float*)p_gsum, (const int*)p_gcnt, lw, lb, out, G);
}

// round 15
// speedup vs baseline: 1.3718x; 1.3718x over previous
#include <cuda_runtime.h>
#include <cstdint>

// Problem constants (shapes are fixed by the dataset).
static constexpr int cN = 300000;
static constexpr int cE = 1500000;
static constexpr int cG = 30000;

// Scratch (device globals — no allocation allowed). Zero-initialized at load;
// the transform kernels re-zero agg1/agg2 each call to keep the invariant.
__device__ float g_x0[(size_t)cN * 32];
__device__ float g_h1[(size_t)cN * 64];
__device__ float g_agg1[(size_t)cN * 3 * 32];   // layer-1 aggregates [N][3][32]
__device__ float g_agg2[(size_t)cN * 3 * 64];   // layer-2 aggregates [N][3][64]
__device__ int   g_cnt[(size_t)cN * 3];
__device__ float g_inv[(size_t)cN * 3];
__device__ float g_gsum[(size_t)cG * 64];
__device__ int   g_gcnt[cG];

// ---------------------------------------------------------------------------
// Packed fp32x2 helpers (kept from the 750us best-known-good configuration).
__device__ __forceinline__ unsigned long long pack2(float x, float y) {
    unsigned long long r;
    asm("mov.b64 %0, {%1, %2};" : "=l"(r)
        : "r"(__float_as_uint(x)), "r"(__float_as_uint(y)));
    return r;
}
__device__ __forceinline__ void ffma2(unsigned long long& d,
                                      unsigned long long a, unsigned long long b) {
    asm("fma.rn.f32x2 %0, %1, %2, %0;" : "+l"(d) : "l"(a), "l"(b));
}
__device__ __forceinline__ void unpack2(unsigned long long v, float& lo, float& hi) {
    unsigned int a, b;
    asm("mov.b64 {%0, %1}, %2;" : "=r"(a), "=r"(b) : "l"(v));
    lo = __uint_as_float(a);
    hi = __uint_as_float(b);
}

// ---------------------------------------------------------------------------
// Merged prologue: edge-relation counts + node features + per-graph node counts.
// Independent index spaces share one grid so their DRAM/atomic phases overlap.
__global__ void prologue_kernel(const int* __restrict__ ei, const int* __restrict__ et,
                                int* __restrict__ cnt,
                                const int* __restrict__ sid, const int* __restrict__ cid,
                                const int* __restrict__ pid,
                                const float* __restrict__ se, const float* __restrict__ ce,
                                const float* __restrict__ pe,
                                float* __restrict__ x0,
                                const int* __restrict__ batch, int* __restrict__ gcnt,
                                int N, int E) {
    int t = blockIdx.x * blockDim.x + threadIdx.x;
    if (t < E) atomicAdd(&cnt[ei[E + t] * 3 + et[t]], 1);
    int n = t >> 3, q = t & 7;
    if (n < N) {
        float4 a = ((const float4*)(se + (size_t)sid[n] * 32))[q];
        float4 b = ((const float4*)(ce + (size_t)cid[n] * 32))[q];
        float4 c = ((const float4*)(pe + (size_t)pid[n] * 32))[q];
        ((float4*)(x0 + (size_t)n * 32))[q] =
            make_float4(a.x + b.x + c.x, a.y + b.y + c.y, a.z + b.z + c.z, a.w + b.w + c.w);
        if (q == 0) atomicAdd(&gcnt[batch[n]], 1);
    }
}

// inv[i] = 1 / max(cnt[i], 1)
__global__ void inv_kernel(const int* __restrict__ cnt, float* __restrict__ inv, int M) {
    int i = blockIdx.x * blockDim.x + threadIdx.x;
    if (i >= M) return;
    inv[i] = __fdividef(1.0f, (float)max(cnt[i], 1));
}

// Edge aggregation: agg[dst][et][*] += x[src][*] * inv[dst][et]
// D/4 lanes per edge; one vector RED (red.global.add.v4.f32) per lane.
template <int D>
__global__ void edge_agg_kernel(const float* __restrict__ xin,
                                const int* __restrict__ ei,
                                const int* __restrict__ et,
                                const float* __restrict__ inv,
                                float* __restrict__ agg, int E) {
    constexpr int L = D / 4;
    int t = blockIdx.x * blockDim.x + threadIdx.x;
    int e = t / L, q = t % L;
    if (e >= E) return;
    int s = ei[e], d = ei[E + e], r = et[e];
    int slot = d * 3 + r;
    float w = inv[slot];
    float4 v = ((const float4*)(xin + (size_t)s * D))[q];
    float* o = agg + (size_t)slot * D + q * 4;
    asm volatile("red.global.add.v4.f32 [%0], {%1, %2, %3, %4};"
                 :: "l"(o), "f"(v.x * w), "f"(v.y * w), "f"(v.z * w), "f"(v.w * w)
                 : "memory");
}

// Fused transform: out[n] = act( b + agg[n] (3D wide) @ vstack(W_r) + x[n] @ root )
// = one logical [N x 4D] @ [4D x 64] GEMM (exact R7 750us configuration).
// Block = 256 threads; tile = 128 nodes. Thread = (group g: 8 nodes) x (lane: 4 outs).
// POOL epilogue: instead of storing h, RED the ReLU'd row into gsum[batch[node]]
// (global mean pool numerator) — h2 is never materialized.
// Also zeroes `zbuf` (the OTHER layer's agg buffer) for the next use.
template <int D, bool RELU, bool POOL>
__global__ void __launch_bounds__(256)
transform_kernel(const float* __restrict__ agg,
                 const float* __restrict__ xin,
                 const float* __restrict__ W,     // [3*D][64]
                 const float* __restrict__ root,  // [D][64]
                 const float* __restrict__ bias,  // [64]
                 float* __restrict__ out,         // h (POOL=false) or gsum (POOL=true)
                 const int* __restrict__ batch,   // used when POOL
                 float* __restrict__ zbuf, int zf4,  // float4s per node to zero
                 int N) {
    constexpr int IN = 4 * D;          // 128 / 256
    constexpr int CH = 64;             // k-chunk staged per pass
    constexpr int NCH = IN / CH;       // 2 / 4
    constexpr int TS = 132;            // k-major row stride (128 nodes + pad)
    extern __shared__ float smem[];
    float4* Ws = (float4*)smem;              // [IN*16]: Ws[k*16+l] = W[k][4l..4l+3]
    float*  ins = smem + (size_t)IN * 64;    // [CH][TS], k-major

    for (int i = threadIdx.x; i < IN * 16; i += 256) {
        int k = i >> 4, l = i & 15;
        const float* row = (k < 3 * D) ? (W + (size_t)k * 64) : (root + (size_t)(k - 3 * D) * 64);
        Ws[i] = ((const float4*)row)[l];
    }

    int lane = threadIdx.x & 15;   // output quad
    int g    = threadIdx.x >> 4;   // node group (8 nodes = 4 pairs)
    float4 b4 = ((const float4*)bias)[lane];
    unsigned long long binit[4] = {pack2(b4.x, b4.x), pack2(b4.y, b4.y),
                                   pack2(b4.z, b4.z), pack2(b4.w, b4.w)};

    for (int tile = blockIdx.x * 128; tile < N; tile += gridDim.x * 128) {
        unsigned long long acc[4][4];  // [node pair][output component]
#pragma unroll
        for (int p = 0; p < 4; p++)
#pragma unroll
            for (int o = 0; o < 4; o++) acc[p][o] = binit[o];

#pragma unroll
        for (int c = 0; c < NCH; c++) {
            __syncthreads();   // covers initial weight load / previous chunk reads
            // Stage chunk c transposed: ins[k - c*CH][node]. Unit i = (kq, n).
            for (int i = threadIdx.x; i < 128 * 16; i += 256) {
                int n = i & 127, kq = i >> 7;          // kq in [0,16) -> 4 k's each
                int node = tile + n;
                float4 v = make_float4(0.f, 0.f, 0.f, 0.f);
                int gq = c * 16 + kq;                  // float4 index within node row
                if (node < N) {
                    if (gq < 3 * D / 4) v = ((const float4*)agg)[(size_t)node * (3 * D / 4) + gq];
                    else                v = ((const float4*)xin)[(size_t)node * (D / 4) + gq - 3 * D / 4];
                }
                float* p0 = ins + (size_t)(kq * 4) * TS + n;
                p0[0]      = v.x;
                p0[TS]     = v.y;
                p0[2 * TS] = v.z;
                p0[3 * TS] = v.w;
            }
            __syncthreads();

            const float* grow = ins + g * 8;
#pragma unroll 8
            for (int k = 0; k < CH; k++) {
                float4 w = Ws[(c * CH + k) * 16 + lane];
                unsigned long long wx = pack2(w.x, w.x);
                unsigned long long wy = pack2(w.y, w.y);
                unsigned long long wz = pack2(w.z, w.z);
                unsigned long long ww = pack2(w.w, w.w);
                const float* row = grow + (size_t)k * TS;
#pragma unroll
                for (int p = 0; p < 4; p++) {
                    unsigned long long v = *(const unsigned long long*)(row + 2 * p);
                    ffma2(acc[p][0], v, wx);
                    ffma2(acc[p][1], v, wy);
                    ffma2(acc[p][2], v, wz);
                    ffma2(acc[p][3], v, ww);
                }
            }
        }

        // Epilogue: acc[p][o].lo -> node tile+g*8+2p, .hi -> node +1.
#pragma unroll
        for (int p = 0; p < 4; p++) {
            float4 r0, r1;
            unpack2(acc[p][0], r0.x, r1.x);
            unpack2(acc[p][1], r0.y, r1.y);
            unpack2(acc[p][2], r0.z, r1.z);
            unpack2(acc[p][3], r0.w, r1.w);
            if (RELU) {
                r0.x = fmaxf(r0.x, 0.f); r0.y = fmaxf(r0.y, 0.f);
                r0.z = fmaxf(r0.z, 0.f); r0.w = fmaxf(r0.w, 0.f);
                r1.x = fmaxf(r1.x, 0.f); r1.y = fmaxf(r1.y, 0.f);
                r1.z = fmaxf(r1.z, 0.f); r1.w = fmaxf(r1.w, 0.f);
            }
            int n0 = tile + g * 8 + 2 * p;
            if (POOL) {
                if (n0 < N) {
                    float* o = out + (size_t)batch[n0] * 64 + lane * 4;
                    asm volatile("red.global.add.v4.f32 [%0], {%1, %2, %3, %4};"
                                 :: "l"(o), "f"(r0.x), "f"(r0.y), "f"(r0.z), "f"(r0.w)
                                 : "memory");
                }
                if (n0 + 1 < N) {
                    float* o = out + (size_t)batch[n0 + 1] * 64 + lane * 4;
                    asm volatile("red.global.add.v4.f32 [%0], {%1, %2, %3, %4};"
                                 :: "l"(o), "f"(r1.x), "f"(r1.y), "f"(r1.z), "f"(r1.w)
                                 : "memory");
                }
            } else {
                if (n0 < N)     ((float4*)(out + (size_t)n0 * 64))[lane] = r0;
                if (n0 + 1 < N) ((float4*)(out + (size_t)(n0 + 1) * 64))[lane] = r1;
            }
        }

        // Zero-fold: clear the other layer's agg buffer for this node tile.
        {
            const float4 z4 = make_float4(0.f, 0.f, 0.f, 0.f);
            size_t lim = (size_t)N * zf4;
            for (int i = threadIdx.x; i < 128 * zf4; i += 256) {
                size_t idx = (size_t)tile * zf4 + i;
                if (idx < lim) ((float4*)zbuf)[idx] = z4;
            }
        }
    }
}

// Final: out[g] = (gsum[g]/max(cnt,1)) @ lin_W + lin_b. One warp per graph.
__global__ void pool_final_kernel(const float* __restrict__ gsum, const int* __restrict__ gcnt,
                                  const float* __restrict__ lw, const float* __restrict__ lb,
                                  float* __restrict__ out, int G) {
    int t = blockIdx.x * blockDim.x + threadIdx.x;
    int g = t >> 5, lane = t & 31;
    if (g >= G) return;
    float2 v = ((const float2*)(gsum + (size_t)g * 64))[lane];
    int k0 = 2 * lane, k1 = 2 * lane + 1;
    float a0 = v.x * lw[k0 * 2 + 0] + v.y * lw[k1 * 2 + 0];
    float a1 = v.x * lw[k0 * 2 + 1] + v.y * lw[k1 * 2 + 1];
#pragma unroll
    for (int off = 16; off; off >>= 1) {
        a0 += __shfl_down_sync(0xffffffff, a0, off);
        a1 += __shfl_down_sync(0xffffffff, a1, off);
    }
    if (lane == 0) {
        float c = fmaxf((float)gcnt[g], 1.0f);
        out[g * 2 + 0] = a0 / c + lb[0];
        out[g * 2 + 1] = a1 / c + lb[1];
    }
}

// ---------------------------------------------------------------------------
extern "C" void kernel_launch(void* const* d_in, const int* in_sizes, int n_in,
                              void* d_out, int out_size) {
    const int*   sid   = (const int*)d_in[0];
    const int*   cid   = (const int*)d_in[1];
    const int*   pid   = (const int*)d_in[2];
    const int*   ei    = (const int*)d_in[3];   // [2, E]: row0 = src, row1 = dst
    const int*   et    = (const int*)d_in[4];
    const int*   batch = (const int*)d_in[5];
    // d_in[6] = num_graphs (scalar), unused
    const float* se = (const float*)d_in[7];
    const float* ce = (const float*)d_in[8];
    const float* pe = (const float*)d_in[9];
    const float* W1 = (const float*)d_in[10];
    const float* r1 = (const float*)d_in[11];
    const float* b1 = (const float*)d_in[12];
    const float* W2 = (const float*)d_in[13];
    const float* r2 = (const float*)d_in[14];
    const float* b2 = (const float*)d_in[15];
    const float* lw = (const float*)d_in[16];
    const float* lb = (const float*)d_in[17];
    float* out = (float*)d_out;

    const int N = in_sizes[0];
    const int E = in_sizes[4];
    const int G = out_size / 2;

    void *p_x0, *p_h1, *p_agg1, *p_agg2, *p_cnt, *p_inv, *p_gsum, *p_gcnt;
    cudaGetSymbolAddress(&p_x0, g_x0);
    cudaGetSymbolAddress(&p_h1, g_h1);
    cudaGetSymbolAddress(&p_agg1, g_agg1);
    cudaGetSymbolAddress(&p_agg2, g_agg2);
    cudaGetSymbolAddress(&p_cnt, g_cnt);
    cudaGetSymbolAddress(&p_inv, g_inv);
    cudaGetSymbolAddress(&p_gsum, g_gsum);
    cudaGetSymbolAddress(&p_gcnt, g_gcnt);

    // smem: layer1 = 128*64*4 + 64*132*4 = 66560 B (3 blocks/SM)
    //       layer2 = 256*64*4 + 64*132*4 = 99328 B (2 blocks/SM)
    cudaFuncSetAttribute(transform_kernel<32, true, false>,
                         cudaFuncAttributeMaxDynamicSharedMemorySize, 70 * 1024);
    cudaFuncSetAttribute(transform_kernel<64, true, true>,
                         cudaFuncAttributeMaxDynamicSharedMemorySize, 100 * 1024);

    cudaMemsetAsync(p_cnt, 0, (size_t)N * 3 * sizeof(int));
    cudaMemsetAsync(p_gsum, 0, (size_t)G * 64 * sizeof(float));
    cudaMemsetAsync(p_gcnt, 0, (size_t)G * sizeof(int));

    // Merged count + features + gcnt.
    {
        int total = N * 8 > E ? N * 8 : E;
        prologue_kernel<<<(total + 255) / 256, 256>>>(
            ei, et, (int*)p_cnt, sid, cid, pid, se, ce, pe, (float*)p_x0,
            batch, (int*)p_gcnt, N, E);
    }
    inv_kernel<<<(N * 3 + 255) / 256, 256>>>((const int*)p_cnt, (float*)p_inv, N * 3);

    // ---- Layer 1 (D = 32) ----
    // agg1 was zeroed by the previous call's transform (or load-time init).
    edge_agg_kernel<32><<<(E * 8 + 255) / 256, 256>>>(
        (const float*)p_x0, ei, et, (const float*)p_inv, (float*)p_agg1, E);
    {
        int smem1 = (128 * 64 + 64 * 132) * (int)sizeof(float);  // 66560 B
        transform_kernel<32, true, false><<<444, 256, smem1>>>(
            (const float*)p_agg1, (const float*)p_x0, W1, r1, b1, (float*)p_h1,
            nullptr, (float*)p_agg2, 3 * 64 / 4, N);   // zero agg2 for layer 2
    }

    // ---- Layer 2 (D = 64), pool fused into epilogue ----
    edge_agg_kernel<64><<<(E * 16 + 255) / 256, 256>>>(
        (const float*)p_h1, ei, et, (const float*)p_inv, (float*)p_agg2, E);
    {
        int smem2 = (256 * 64 + 64 * 132) * (int)sizeof(float);  // 99328 B
        transform_kernel<64, true, true><<<296, 256, smem2>>>(
            (const float*)p_agg2, (const float*)p_h1, W2, r2, b2, (float*)p_gsum,
            batch, (float*)p_agg1, 3 * 32 / 4, N);   // zero agg1 for the next call
    }

    // ---- Head ----
    pool_final_kernel<<<(G * 32 + 255) / 256, 256>>>(
        (const float*)p_gsum, (const int*)p_gcnt, lw, lb, out, G);
}